// round 15
// baseline (speedup 1.0000x reference)
#include <cuda_runtime.h>
#include <cuda_fp16.h>

#define LFRAMES 120000
#define C       256
#define TL      128
#define NBLK    938       // ceil(120000/128); last tile has 64 valid rows
#define NTH     256
#define TSAMP   600000
#define TLF     64

#define ASTRIDE 128       // u32 row stride of A images (XOR-swizzled 16B cols)
#define ALO_OFF (TL*ASTRIDE*4)
#define KSTR    16        // u32 row stride of B smem (XOR-swizzled 16B cols)
#define BHALF   4096      // 256*16 u32 per half (hi or lo) of one K=32 chunk
#define BSTAGE  8192      // hi+lo per stage (u32)
#define BIMG    32768     // 256*128 u32 per half image in global

typedef unsigned int u32;

__device__ float g_bufA[LFRAMES * C];
__device__ float g_bufB[LFRAMES * C];
// 6 matrices x {hi,lo}: packed f16x2 images [n][k2], row stride 128
__device__ __align__(16) u32 g_Bimg[12 * BIMG];

__device__ __forceinline__ float leakyf(float x) { return x >= 0.0f ? x : 0.3f * x; }
__device__ __forceinline__ float quant_div(float x, float s, float o) {
    float q = rintf(x / s - o);
    return fminf(fmaxf(q, -128.0f), 127.0f);
}
__device__ __forceinline__ float quant_mul(float x, float is, float o) {
    float q = rintf(x * is - o);
    return fminf(fmaxf(q, -128.0f), 127.0f);
}
__device__ __forceinline__ void split2(float a, float b, u32& hi, u32& lo) {
    __half ha = __float2half_rn(a), hb = __float2half_rn(b);
    __half2 h2 = __halves2half2(ha, hb);
    hi = *reinterpret_cast<u32*>(&h2);
    __half2 l2 = __floats2half2_rn(a - __half2float(ha), b - __half2float(hb));
    lo = *reinterpret_cast<u32*>(&l2);
}
__device__ __forceinline__ void mma16816(float* d, const u32* a, u32 b0, u32 b1) {
    asm volatile("mma.sync.aligned.m16n8k16.row.col.f32.f16.f16.f32 "
                 "{%0,%1,%2,%3}, {%4,%5,%6,%7}, {%8,%9}, {%0,%1,%2,%3};"
                 : "+f"(d[0]), "+f"(d[1]), "+f"(d[2]), "+f"(d[3])
                 : "r"(a[0]), "r"(a[1]), "r"(a[2]), "r"(a[3]), "r"(b0), "r"(b1));
}
__device__ __forceinline__ void ldm_x4(u32* r, u32 addr) {
    asm volatile("ldmatrix.sync.aligned.m8n8.x4.shared.b16 {%0,%1,%2,%3}, [%4];"
                 : "=r"(r[0]), "=r"(r[1]), "=r"(r[2]), "=r"(r[3]) : "r"(addr));
}
__device__ __forceinline__ u32 smem_u32(const void* p) {
    u32 a; asm("{ .reg .u64 t; cvta.to.shared.u64 t, %1; cvt.u32.u64 %0, t; }"
               : "=r"(a) : "l"(p));
    return a;
}
__device__ __forceinline__ void cpa16(u32 dst, const u32* src) {
    asm volatile("{ .reg .u64 g; cvta.to.global.u64 g, %1;"
                 " cp.async.cg.shared.global [%0], [g], 16; }"
                 :: "r"(dst), "l"(src));
}
__device__ __forceinline__ void cpa_commit() {
    asm volatile("cp.async.commit_group;" ::: "memory");
}
template <int N> __device__ __forceinline__ void cpa_wait() {
    asm volatile("cp.async.wait_group %0;" :: "n"(N) : "memory");
}

// A-image swizzled u32 index for element (row m, k2 cp)
__device__ __forceinline__ int aidx(int m, int cp) {
    return m * ASTRIDE + ((((cp >> 2) ^ (m & 7)) << 2) | (cp & 3));
}

// -------------------------------------------------------------------------
// Prep: weights -> split f16x2 images, [n][k2], row stride 128.
// -------------------------------------------------------------------------
__global__ void k_prep(const float* __restrict__ w0, const float* __restrict__ w1,
                       const float* __restrict__ w2, const float* __restrict__ w3,
                       const float* __restrict__ w4, const float* __restrict__ w5)
{
    const float* Ws[6] = {w0, w1, w2, w3, w4, w5};
    const int m = blockIdx.y;
    const int idx = blockIdx.x * 256 + threadIdx.x;   // 0..32767
    const int n = idx >> 7, k2 = idx & 127;
    float v0 = Ws[m][(2 * k2) * C + n];
    float v1 = Ws[m][(2 * k2 + 1) * C + n];
    u32 hi, lo;
    split2(v0, v1, hi, lo);
    g_Bimg[(size_t)(2 * m) * BIMG + n * 128 + k2]     = hi;
    g_Bimg[(size_t)(2 * m + 1) * BIMG + n * 128 + k2] = lo;
}

// -------------------------------------------------------------------------
// First conv (k=10, stride=5, 1->256) + bias
// -------------------------------------------------------------------------
__global__ __launch_bounds__(256) void k_first(
    const float* __restrict__ x, const float* __restrict__ fb,
    const float* __restrict__ wf, const float* __restrict__ bf,
    float* __restrict__ res)
{
    __shared__ float sx[5 * TLF + 10];
    const int l0  = blockIdx.x * TLF;
    const int tid = threadIdx.x;
    const int base = 5 * l0;
    for (int i = tid; i < 5 * TLF + 10; i += 256) {
        int t = base + i;
        float v;
        if (t < 5)              v = fb[t];
        else if (t - 5 < TSAMP) v = x[t - 5];
        else                    v = 0.0f;
        sx[i] = v;
    }
    float w[10];
#pragma unroll
    for (int k = 0; k < 10; k++) w[k] = wf[k * C + tid];
    const float b = bf[tid];
    __syncthreads();
    for (int f = 0; f < TLF; f++) {
        float acc = b;
#pragma unroll
        for (int k = 0; k < 10; k++) acc = fmaf(sx[5 * f + k], w[k], acc);
        res[(l0 + f) * C + tid] = acc;
    }
}

// prefetch one K=32 chunk into a stage (swizzled B layout); 256 threads
__device__ __forceinline__ void prefetch_chunk(
    u32 stage_addr, const u32* __restrict__ img, int cc, int tid)
{
#pragma unroll
    for (int j = 0; j < 4; j++) {
        const int idx = tid + j * NTH;        // 0..1023
        const int n = idx >> 2, jj = idx & 3;
        const u32 col = (u32)(jj ^ ((n >> 1) & 3));
        const u32 d = stage_addr + (u32)(n * KSTR + col * 4) * 4u;
        const u32* s = img + n * 128 + cc * 16 + jj * 4;
        cpa16(d, s);
        cpa16(d + BHALF * 4u, s + BIMG);      // lo half follows hi
    }
}

// -------------------------------------------------------------------------
// Fused residual block: 128 rows x 256 ch per CTA, 256 threads, 8 warps.
// Warp tile 64x64 (grid 2M x 4N). 255 regs/thread, f16 3-product split.
// -------------------------------------------------------------------------
template <int MODE, int DIL>
__global__ __launch_bounds__(NTH, 1) void k_block(
    const float* __restrict__ src,  const float* __restrict__ cbuf,
    const float* __restrict__ wdw,  const float* __restrict__ bdw,
    const float* __restrict__ bpw,  const float* __restrict__ blc,
    const u32* __restrict__ imgs,   // [pwHi, pwLo, lcHi, lcLo] x BIMG
    float* __restrict__ dst)
{
    constexpr int PAD = 2 * DIL;
    constexpr float S2 = 5.548006534576416f;
    constexpr float S3 = 4.458680152893066f;
    constexpr float INV_Q1  = (float)(1.0 / 17.62967872619629);
    constexpr float INV_RQ1 = (float)(1.0 / 12.716455459594727);
    constexpr float INV_S3  = (float)(1.0 / 4.458680152893066);

    extern __shared__ u32 smu[];
    u32* sHhi = smu;                          // TL*ASTRIDE
    u32* sHlo = smu + TL * ASTRIDE;
    float* sLUT = (float*)(smu + 2 * TL * ASTRIDE);   // 256
    u32* sB = smu + 2 * TL * ASTRIDE + 256;   // 3 stages x BSTAGE
    const u32 sB_addr = smem_u32(sB);
    const u32 sHhi_a  = smem_u32(sHhi);

    const int tid  = threadIdx.x;
    const int w    = tid >> 5;
    const int lane = tid & 31;
    const int q    = lane & 3;
    const int g    = lane >> 2;
    const int mw   = (w & 1) * 64;            // 2-way M grid
    const int nw   = (w >> 1) * 64;           // 4-way N grid
    const int l0   = blockIdx.x * TL;

    // ldmatrix lane bases (tile index tA = lane>>3, row-in-tile iA = lane&7)
    const int tA = lane >> 3, iA = lane & 7;
    u32 aRow[4];  int aXor[4];
#pragma unroll
    for (int mt = 0; mt < 4; mt++) {
        const int row = mw + mt * 16 + (tA & 1) * 8 + iA;
        aRow[mt] = sHhi_a + (u32)(row * ASTRIDE) * 4u;
        aXor[mt] = row & 7;
    }
    const int aColBase = tA >> 1;
    u32 bRow[4];  int bXor[4];
#pragma unroll
    for (int nbp = 0; nbp < 4; nbp++) {
        const int n = nw + nbp * 16 + (tA >> 1) * 8 + iA;
        bRow[nbp] = sB_addr + (u32)(n * KSTR) * 4u;
        bXor[nbp] = (n >> 1) & 3;
    }
    const int bColBase = tA & 1;

    // LUT: n -> quant(dequant(leaky(n))) exact (S2/47); MODE1 epi, MODE2 dw.
    sLUT[tid] = quant_div((leakyf((float)(tid - 128)) + 47.0f) * S2, S2, 47.0f);

    // preload chunks 0 and 1 (overlap with depthwise)
    prefetch_chunk(sB_addr, imgs, 0, tid);
    cpa_commit();
    prefetch_chunk(sB_addr + BSTAGE * 4u, imgs, 1, tid);
    cpa_commit();

    if (MODE == 2) __syncthreads();   // LUT visible before depthwise uses it

    // ---- depthwise (k=3, dil=DIL); ci computed inline from src -> sH
    {
        const int cp = tid & 127;       // channel pair (= k2)
        const int c0 = cp * 2;
        const int mb = tid >> 7;        // 0..1
        const float2 wd0 = *(const float2*)(wdw + c0);
        const float2 wd1 = *(const float2*)(wdw + C + c0);
        const float2 wd2 = *(const float2*)(wdw + 2 * C + c0);
        const float2 bb  = *(const float2*)(bdw + c0);
#pragma unroll 4
        for (int j = 0; j < 64; j++) {
            const int m = mb + j * 2;
            const int tt = l0 + m;
            float2 xs[3];
#pragma unroll
            for (int tap = 0; tap < 3; tap++) {
                const int t = tt - (2 - tap) * DIL;
                if (t >= 0) {
                    float2 r = *(const float2*)(src + (size_t)min(t, LFRAMES - 1) * C + c0);
                    if (MODE == 1) {
                        xs[tap].x = leakyf(r.x);
                        xs[tap].y = leakyf(r.y);
                    } else if (MODE == 2) {
                        xs[tap].x = sLUT[(int)r.x + 128];
                        xs[tap].y = sLUT[(int)r.y + 128];
                    } else {
                        xs[tap].x = quant_mul((leakyf(r.x) + 38.0f) * S3, INV_S3, 38.0f);
                        xs[tap].y = quant_mul((leakyf(r.y) + 38.0f) * S3, INV_S3, 38.0f);
                    }
                } else {
                    float2 bv = *(const float2*)(cbuf + (t + PAD) * C + c0);
                    if (MODE == 1) xs[tap] = bv;
                    else if (MODE == 2) {
                        xs[tap].x = quant_div(bv.x, S2, 47.0f);
                        xs[tap].y = quant_div(bv.y, S2, 47.0f);
                    } else {
                        xs[tap].x = quant_div(bv.x, S3, 38.0f);
                        xs[tap].y = quant_div(bv.y, S3, 38.0f);
                    }
                }
            }
            float h0 = bb.x, h1 = bb.y;
            h0 = fmaf(xs[0].x, wd0.x, h0); h1 = fmaf(xs[0].y, wd0.y, h1);
            h0 = fmaf(xs[1].x, wd1.x, h0); h1 = fmaf(xs[1].y, wd1.y, h1);
            h0 = fmaf(xs[2].x, wd2.x, h0); h1 = fmaf(xs[2].y, wd2.y, h1);
            u32 hi, lo;
            split2(h0, h1, hi, lo);
            const int ai = aidx(m, cp);
            sHhi[ai] = hi;
            sHlo[ai] = lo;
        }
    }

    // ---- acc init for GEMM1
    float acc[4][8][4];
#pragma unroll
    for (int nb = 0; nb < 8; nb++) {
        const int cn = nw + nb * 8 + q * 2;
        float b0 = bpw[cn], b1 = bpw[cn + 1];
#pragma unroll
        for (int mt = 0; mt < 4; mt++) {
            acc[mt][nb][0] = b0; acc[mt][nb][1] = b1;
            acc[mt][nb][2] = b0; acc[mt][nb][3] = b1;
        }
    }

    // ---- 16-chunk pipeline: 0..7 GEMM1 (pw), 8..15 GEMM2 (lc)
    for (int c = 0; c < 16; c++) {
        if (c < 15) cpa_wait<1>(); else cpa_wait<0>();
        __syncthreads();

        if (c + 2 < 16) {
            const int nc = c + 2;
            const u32* ih = (nc < 8) ? imgs : (imgs + 2 * BIMG);
            prefetch_chunk(sB_addr + (u32)(nc % 3) * (BSTAGE * 4u), ih, nc & 7, tid);
            cpa_commit();
        }

        if (c == 8) {
            // epilogue1: P -> quant/leaky -> split -> sH; re-init acc
#pragma unroll
            for (int mt = 0; mt < 4; mt++) {
                const int r0 = mw + mt * 16 + g;
#pragma unroll
                for (int nb = 0; nb < 8; nb++) {
                    const int k2p = nw / 2 + nb * 4 + q;
                    float p0 = acc[mt][nb][0], p1 = acc[mt][nb][1];
                    float p2 = acc[mt][nb][2], p3 = acc[mt][nb][3];
                    if (MODE == 1) {
                        p0 = quant_mul(p0, INV_Q1, -67.0f);
                        p1 = quant_mul(p1, INV_Q1, -67.0f);
                        p2 = quant_mul(p2, INV_Q1, -67.0f);
                        p3 = quant_mul(p3, INV_Q1, -67.0f);
                    }
                    p0 = leakyf(p0); p1 = leakyf(p1);
                    p2 = leakyf(p2); p3 = leakyf(p3);
                    u32 hi, lo;
                    split2(p0, p1, hi, lo);
                    int ai = aidx(r0, k2p);
                    sHhi[ai] = hi;  sHlo[ai] = lo;
                    split2(p2, p3, hi, lo);
                    ai = aidx(r0 + 8, k2p);
                    sHhi[ai] = hi;  sHlo[ai] = lo;
                }
            }
#pragma unroll
            for (int nb = 0; nb < 8; nb++) {
                const int cn = nw + nb * 8 + q * 2;
                float b0 = blc[cn], b1 = blc[cn + 1];
#pragma unroll
                for (int mt = 0; mt < 4; mt++) {
                    acc[mt][nb][0] = b0; acc[mt][nb][1] = b1;
                    acc[mt][nb][2] = b0; acc[mt][nb][3] = b1;
                }
            }
            __syncthreads();
        }

        // ---- MMA on chunk c (ldmatrix, product-major ordering)
        const int cc = c & 7;
        const u32 stOff = (u32)(c % 3) * (BSTAGE * 4u);
#pragma unroll
        for (int sp = 0; sp < 2; sp++) {
            u32 ah[4][4], al[4][4];
#pragma unroll
            for (int mt = 0; mt < 4; mt++) {
                const int colA = cc * 4 + sp * 2 + aColBase;
                const u32 aoff = (u32)((colA ^ aXor[mt]) << 4);
                ldm_x4(ah[mt], aRow[mt] + aoff);
                ldm_x4(al[mt], aRow[mt] + aoff + (u32)ALO_OFF);
            }
#pragma unroll
            for (int nbq = 0; nbq < 2; nbq++) {
                u32 bh[2][4], bl[2][4];
#pragma unroll
                for (int t = 0; t < 2; t++) {
                    const int nbp = nbq * 2 + t;
                    const int colB = sp * 2 + bColBase;
                    const u32 bo = bRow[nbp] + stOff + (u32)((colB ^ bXor[nbp]) << 4);
                    ldm_x4(bh[t], bo);
                    ldm_x4(bl[t], bo + (u32)(BHALF * 4));
                }
                // product-major: same-acc reuse distance = 16 MMAs
#pragma unroll
                for (int t = 0; t < 2; t++)
#pragma unroll
                    for (int j = 0; j < 2; j++)
#pragma unroll
                        for (int mt = 0; mt < 4; mt++)
                            mma16816(acc[mt][(nbq * 2 + t) * 2 + j],
                                     ah[mt], bh[t][2 * j], bh[t][2 * j + 1]);
#pragma unroll
                for (int t = 0; t < 2; t++)
#pragma unroll
                    for (int j = 0; j < 2; j++)
#pragma unroll
                        for (int mt = 0; mt < 4; mt++)
                            mma16816(acc[mt][(nbq * 2 + t) * 2 + j],
                                     al[mt], bh[t][2 * j], bh[t][2 * j + 1]);
#pragma unroll
                for (int t = 0; t < 2; t++)
#pragma unroll
                    for (int j = 0; j < 2; j++)
#pragma unroll
                        for (int mt = 0; mt < 4; mt++)
                            mma16816(acc[mt][(nbq * 2 + t) * 2 + j],
                                     ah[mt], bl[t][2 * j], bl[t][2 * j + 1]);
            }
        }
    }

    // ---- final epilogue: residual + mode-specific output
#pragma unroll
    for (int mt = 0; mt < 4; mt++) {
#pragma unroll
        for (int nb = 0; nb < 8; nb++) {
            const int cn = nw + nb * 8 + q * 2;
#pragma unroll
            for (int half = 0; half < 2; half++) {
                const int l = l0 + mw + mt * 16 + g + half * 8;
                if (l >= LFRAMES) continue;
                float o0 = acc[mt][nb][half * 2];
                float o1 = acc[mt][nb][half * 2 + 1];
                float2 r = *(const float2*)(src + (size_t)l * C + cn);
                float2 val;
                if (MODE == 1) {
                    val.x = quant_mul(r.x + (o0 - 16.0f) * 6.528060436248779f, INV_RQ1, -23.0f);
                    val.y = quant_mul(r.y + (o1 - 16.0f) * 6.528060436248779f, INV_RQ1, -23.0f);
                } else if (MODE == 2) {
                    val.x = o0 + r.x;
                    val.y = o1 + r.y;
                } else {
                    val.x = (leakyf(o0 + r.x) + 34.0f) * 3.698859930038452f;
                    val.y = (leakyf(o1 + r.y) + 34.0f) * 3.698859930038452f;
                }
                *(float2*)(dst + (size_t)l * C + cn) = val;
            }
        }
    }
}

// -------------------------------------------------------------------------
extern "C" void kernel_launch(void* const* d_in, const int* in_sizes, int n_in,
                              void* d_out, int out_size)
{
    (void)in_sizes; (void)n_in; (void)out_size;
    const float* x    = (const float*)d_in[0];
    const float* fb   = (const float*)d_in[1];
    const float* r1b  = (const float*)d_in[2];
    const float* r2b  = (const float*)d_in[3];
    const float* r3b  = (const float*)d_in[4];
    const float* wf   = (const float*)d_in[5];
    const float* bf   = (const float*)d_in[6];
    const float* wdw1 = (const float*)d_in[7],  *bdw1 = (const float*)d_in[8];
    const float* wpw1 = (const float*)d_in[9],  *bpw1 = (const float*)d_in[10];
    const float* wlc1 = (const float*)d_in[11], *blc1 = (const float*)d_in[12];
    const float* wdw2 = (const float*)d_in[13], *bdw2 = (const float*)d_in[14];
    const float* wpw2 = (const float*)d_in[15], *bpw2 = (const float*)d_in[16];
    const float* wlc2 = (const float*)d_in[17], *blc2 = (const float*)d_in[18];
    const float* wdw3 = (const float*)d_in[19], *bdw3 = (const float*)d_in[20];
    const float* wpw3 = (const float*)d_in[21], *bpw3 = (const float*)d_in[22];
    const float* wlc3 = (const float*)d_in[23], *blc3 = (const float*)d_in[24];
    float* out = (float*)d_out;

    float *bufA, *bufB;
    u32* img;
    cudaGetSymbolAddress((void**)&bufA, g_bufA);
    cudaGetSymbolAddress((void**)&bufB, g_bufB);
    cudaGetSymbolAddress((void**)&img,  g_Bimg);

    const int SMB = (2 * TL * ASTRIDE + 256 + 3 * BSTAGE) * 4;  // 230,400 B
    cudaFuncSetAttribute(k_block<1, 1>, cudaFuncAttributeMaxDynamicSharedMemorySize, SMB);
    cudaFuncSetAttribute(k_block<2, 3>, cudaFuncAttributeMaxDynamicSharedMemorySize, SMB);
    cudaFuncSetAttribute(k_block<3, 9>, cudaFuncAttributeMaxDynamicSharedMemorySize, SMB);

    k_prep<<<dim3(128, 6), 256>>>(wpw1, wlc1, wpw2, wlc2, wpw3, wlc3);
    k_first<<<LFRAMES / TLF, 256>>>(x, fb, wf, bf, bufA);
    k_block<1, 1><<<NBLK, NTH, SMB>>>(bufA, r1b, wdw1, bdw1, bpw1, blc1,
                                      img + 0 * BIMG, bufB);
    k_block<2, 3><<<NBLK, NTH, SMB>>>(bufB, r2b, wdw2, bdw2, bpw2, blc2,
                                      img + 4 * BIMG, bufA);
    k_block<3, 9><<<NBLK, NTH, SMB>>>(bufA, r3b, wdw3, bdw3, bpw3, blc3,
                                      img + 8 * BIMG, out);
}

// round 17
// speedup vs baseline: 1.4755x; 1.4755x over previous
#include <cuda_runtime.h>
#include <cuda_fp16.h>

#define LFRAMES 120000
#define C       256
#define TL      128
#define NBLK    938
#define NTH     512
#define TSAMP   600000
#define TLF     64

#define ASTRIDE 128       // u32 row stride of A images (XOR-swizzled 16B cols)
#define ALO_OFF (TL*ASTRIDE*4)
#define KSTR    16        // u32 row stride of B smem (XOR-swizzled 16B cols)
#define BHALF   4096      // 256*16 u32 per half (hi or lo) of one K=32 chunk
#define BSTAGE  8192      // hi+lo per stage (u32)
#define BIMG    32768     // 256*128 u32 per half image in global

typedef unsigned int u32;

__device__ float g_bufA[LFRAMES * C];   // res ping
__device__ float g_bufB[LFRAMES * C];   // res pong
__device__ float g_bufC[LFRAMES * C];   // ci stream (blocks 1,3)
__device__ float g_bufD[LFRAMES * C];   // ci stream (block 2)
// 6 matrices x {hi,lo}: packed f16x2 images [n][k2], row stride 128
__device__ __align__(16) u32 g_Bimg[12 * BIMG];

__device__ __forceinline__ float leakyf(float x) { return x >= 0.0f ? x : 0.3f * x; }
__device__ __forceinline__ float quant_div(float x, float s, float o) {
    float q = rintf(x / s - o);
    return fminf(fmaxf(q, -128.0f), 127.0f);
}
__device__ __forceinline__ float quant_mul(float x, float is, float o) {
    float q = rintf(x * is - o);
    return fminf(fmaxf(q, -128.0f), 127.0f);
}
__device__ __forceinline__ void split2(float a, float b, u32& hi, u32& lo) {
    __half ha = __float2half_rn(a), hb = __float2half_rn(b);
    __half2 h2 = __halves2half2(ha, hb);
    hi = *reinterpret_cast<u32*>(&h2);
    __half2 l2 = __floats2half2_rn(a - __half2float(ha), b - __half2float(hb));
    lo = *reinterpret_cast<u32*>(&l2);
}
__device__ __forceinline__ void mma16816(float* d, const u32* a, u32 b0, u32 b1) {
    asm volatile("mma.sync.aligned.m16n8k16.row.col.f32.f16.f16.f32 "
                 "{%0,%1,%2,%3}, {%4,%5,%6,%7}, {%8,%9}, {%0,%1,%2,%3};"
                 : "+f"(d[0]), "+f"(d[1]), "+f"(d[2]), "+f"(d[3])
                 : "r"(a[0]), "r"(a[1]), "r"(a[2]), "r"(a[3]), "r"(b0), "r"(b1));
}
__device__ __forceinline__ void ldm_x4(u32* r, u32 addr) {
    asm volatile("ldmatrix.sync.aligned.m8n8.x4.shared.b16 {%0,%1,%2,%3}, [%4];"
                 : "=r"(r[0]), "=r"(r[1]), "=r"(r[2]), "=r"(r[3]) : "r"(addr));
}
__device__ __forceinline__ u32 smem_u32(const void* p) {
    u32 a; asm("{ .reg .u64 t; cvta.to.shared.u64 t, %1; cvt.u32.u64 %0, t; }"
               : "=r"(a) : "l"(p));
    return a;
}
__device__ __forceinline__ void cpa16(u32 dst, const u32* src) {
    asm volatile("{ .reg .u64 g; cvta.to.global.u64 g, %1;"
                 " cp.async.cg.shared.global [%0], [g], 16; }"
                 :: "r"(dst), "l"(src));
}
__device__ __forceinline__ void cpa_commit() {
    asm volatile("cp.async.commit_group;" ::: "memory");
}
template <int N> __device__ __forceinline__ void cpa_wait() {
    asm volatile("cp.async.wait_group %0;" :: "n"(N) : "memory");
}

// A-image swizzled u32 index for element (row m, k2 cp)
__device__ __forceinline__ int aidx(int m, int cp) {
    return m * ASTRIDE + ((((cp >> 2) ^ (m & 7)) << 2) | (cp & 3));
}

// -------------------------------------------------------------------------
// Prep: weights -> split f16x2 images, [n][k2], row stride 128.
// -------------------------------------------------------------------------
__global__ void k_prep(const float* __restrict__ w0, const float* __restrict__ w1,
                       const float* __restrict__ w2, const float* __restrict__ w3,
                       const float* __restrict__ w4, const float* __restrict__ w5)
{
    const float* Ws[6] = {w0, w1, w2, w3, w4, w5};
    const int m = blockIdx.y;
    const int idx = blockIdx.x * 256 + threadIdx.x;   // 0..32767
    const int n = idx >> 7, k2 = idx & 127;
    float v0 = Ws[m][(2 * k2) * C + n];
    float v1 = Ws[m][(2 * k2 + 1) * C + n];
    u32 hi, lo;
    split2(v0, v1, hi, lo);
    g_Bimg[(size_t)(2 * m) * BIMG + n * 128 + k2]     = hi;
    g_Bimg[(size_t)(2 * m + 1) * BIMG + n * 128 + k2] = lo;
}

// -------------------------------------------------------------------------
// First conv (k=10, stride=5, 1->256) + bias; emits res + ci1 = leaky(res)
// -------------------------------------------------------------------------
__global__ __launch_bounds__(256) void k_first(
    const float* __restrict__ x, const float* __restrict__ fb,
    const float* __restrict__ wf, const float* __restrict__ bf,
    float* __restrict__ res, float* __restrict__ ci)
{
    __shared__ float sx[5 * TLF + 10];
    const int l0  = blockIdx.x * TLF;
    const int tid = threadIdx.x;
    const int base = 5 * l0;
    for (int i = tid; i < 5 * TLF + 10; i += 256) {
        int t = base + i;
        float v;
        if (t < 5)              v = fb[t];
        else if (t - 5 < TSAMP) v = x[t - 5];
        else                    v = 0.0f;
        sx[i] = v;
    }
    float w[10];
#pragma unroll
    for (int k = 0; k < 10; k++) w[k] = wf[k * C + tid];
    const float b = bf[tid];
    __syncthreads();
    for (int f = 0; f < TLF; f++) {
        float acc = b;
#pragma unroll
        for (int k = 0; k < 10; k++) acc = fmaf(sx[5 * f + k], w[k], acc);
        res[(l0 + f) * C + tid] = acc;
        ci[(l0 + f) * C + tid]  = leakyf(acc);
    }
}

// prefetch one K=32 chunk into a stage (swizzled B layout); optional lo half
__device__ __forceinline__ void prefetch_chunk(
    u32 stage_addr, const u32* __restrict__ img, int cc, int tid, bool withLo)
{
#pragma unroll
    for (int j = 0; j < 2; j++) {
        const int idx = tid + j * NTH;        // 0..1023
        const int n = idx >> 2, jj = idx & 3;
        const u32 col = (u32)(jj ^ ((n >> 1) & 3));
        const u32 d = stage_addr + (u32)(n * KSTR + col * 4) * 4u;
        const u32* s = img + n * 128 + cc * 16 + jj * 4;
        cpa16(d, s);
        if (withLo) cpa16(d + BHALF * 4u, s + BIMG);
    }
}

// -------------------------------------------------------------------------
// Fused residual block: 128 rows x 256 ch per CTA, 512 threads, 16 warps.
// FB1/FB2: use full 3-product split for GEMM1/GEMM2 (false = 2-product).
// -------------------------------------------------------------------------
template <int MODE, int DIL, bool FB1, bool FB2>
__global__ __launch_bounds__(NTH, 1) void k_block(
    const float* __restrict__ src,  const float* __restrict__ ciG,
    const float* __restrict__ cbuf,
    const float* __restrict__ wdw,  const float* __restrict__ bdw,
    const float* __restrict__ bpw,  const float* __restrict__ blc,
    const u32* __restrict__ imgs,   // [pwHi, pwLo, lcHi, lcLo] x BIMG
    float* __restrict__ dst,        float* __restrict__ ciOut)
{
    constexpr int PAD = 2 * DIL;
    constexpr float S2 = 5.548006534576416f;
    constexpr float S3 = 4.458680152893066f;
    constexpr float INV_Q1  = (float)(1.0 / 17.62967872619629);
    constexpr float INV_RQ1 = (float)(1.0 / 12.716455459594727);
    constexpr float INV_S3  = (float)(1.0 / 4.458680152893066);

    extern __shared__ u32 smu[];
    u32* sHhi = smu;                          // TL*ASTRIDE
    u32* sHlo = smu + TL * ASTRIDE;
    float* sLUT = (float*)(smu + 2 * TL * ASTRIDE);   // 256
    u32* sB = smu + 2 * TL * ASTRIDE + 256;   // 3 stages x BSTAGE
    const u32 sB_addr = smem_u32(sB);
    const u32 sHhi_a  = smem_u32(sHhi);

    const int tid  = threadIdx.x;
    const int w    = tid >> 5;
    const int lane = tid & 31;
    const int q    = lane & 3;
    const int g    = lane >> 2;
    const int mw   = (w & 3) * 32;
    const int nw   = (w >> 2) * 64;
    const int l0   = blockIdx.x * TL;

    // ldmatrix lane bases (tile index tA = lane>>3, row-in-tile iA = lane&7)
    const int tA = lane >> 3, iA = lane & 7;
    u32 aRow[2];  int aXor[2];
#pragma unroll
    for (int mt = 0; mt < 2; mt++) {
        const int row = mw + mt * 16 + (tA & 1) * 8 + iA;
        aRow[mt] = sHhi_a + (u32)(row * ASTRIDE) * 4u;
        aXor[mt] = row & 7;
    }
    const int aColBase = tA >> 1;
    u32 bRow[4];  int bXor[4];
#pragma unroll
    for (int nbp = 0; nbp < 4; nbp++) {
        const int n = nw + nbp * 16 + (tA >> 1) * 8 + iA;
        bRow[nbp] = sB_addr + (u32)(n * KSTR) * 4u;
        bXor[nbp] = (n >> 1) & 3;
    }
    const int bColBase = tA & 1;

    if (MODE == 1 && tid < 256)
        sLUT[tid] = quant_div((leakyf((float)(tid - 128)) + 47.0f) * S2, S2, 47.0f);

    // preload chunks 0 and 1 (overlap with depthwise)
    prefetch_chunk(sB_addr, imgs, 0, tid, FB1);
    cpa_commit();
    prefetch_chunk(sB_addr + BSTAGE * 4u, imgs, 1, tid, FB1);
    cpa_commit();

    // ---- depthwise (k=3, dil=DIL) from global ci stream -> sH images
    {
        const int cp = tid & 127;
        const int c0 = cp * 2;
        const int mb = tid >> 7;        // 0..3
        const float2 wd0 = *(const float2*)(wdw + c0);
        const float2 wd1 = *(const float2*)(wdw + C + c0);
        const float2 wd2 = *(const float2*)(wdw + 2 * C + c0);
        const float2 bb  = *(const float2*)(bdw + c0);
#pragma unroll 4
        for (int j = 0; j < 32; j++) {
            const int m = mb + j * 4;
            const int tt = l0 + m;
            const int t0 = tt - 2 * DIL;
            const int t1 = tt - DIL;
            float2 x0, x1, x2;
            if (t0 >= 0) x0 = *(const float2*)(ciG + (size_t)min(t0, LFRAMES - 1) * C + c0);
            else {
                float2 bv = *(const float2*)(cbuf + (t0 + PAD) * C + c0);
                if (MODE == 1) x0 = bv;
                else if (MODE == 2) { x0.x = quant_div(bv.x, S2, 47.0f); x0.y = quant_div(bv.y, S2, 47.0f); }
                else { x0.x = quant_div(bv.x, S3, 38.0f); x0.y = quant_div(bv.y, S3, 38.0f); }
            }
            if (t1 >= 0) x1 = *(const float2*)(ciG + (size_t)min(t1, LFRAMES - 1) * C + c0);
            else {
                float2 bv = *(const float2*)(cbuf + (t1 + PAD) * C + c0);
                if (MODE == 1) x1 = bv;
                else if (MODE == 2) { x1.x = quant_div(bv.x, S2, 47.0f); x1.y = quant_div(bv.y, S2, 47.0f); }
                else { x1.x = quant_div(bv.x, S3, 38.0f); x1.y = quant_div(bv.y, S3, 38.0f); }
            }
            x2 = *(const float2*)(ciG + (size_t)min(tt, LFRAMES - 1) * C + c0);
            float h0 = bb.x, h1 = bb.y;
            h0 = fmaf(x0.x, wd0.x, h0); h1 = fmaf(x0.y, wd0.y, h1);
            h0 = fmaf(x1.x, wd1.x, h0); h1 = fmaf(x1.y, wd1.y, h1);
            h0 = fmaf(x2.x, wd2.x, h0); h1 = fmaf(x2.y, wd2.y, h1);
            u32 hi, lo;
            split2(h0, h1, hi, lo);
            const int ai = aidx(m, cp);
            sHhi[ai] = hi;
            sHlo[ai] = lo;
        }
    }

    // ---- acc init for GEMM1
    float acc[2][8][4];
#pragma unroll
    for (int nb = 0; nb < 8; nb++) {
        const int cn = nw + nb * 8 + q * 2;
        float b0 = bpw[cn], b1 = bpw[cn + 1];
#pragma unroll
        for (int mt = 0; mt < 2; mt++) {
            acc[mt][nb][0] = b0; acc[mt][nb][1] = b1;
            acc[mt][nb][2] = b0; acc[mt][nb][3] = b1;
        }
    }

    // ---- 16-chunk pipeline: 0..7 GEMM1 (pw), 8..15 GEMM2 (lc)
    for (int c = 0; c < 16; c++) {
        if (c < 15) cpa_wait<1>(); else cpa_wait<0>();
        __syncthreads();

        if (c + 2 < 16) {
            const int nc = c + 2;
            const u32* ih = (nc < 8) ? imgs : (imgs + 2 * BIMG);
            const bool lo = (nc < 8) ? FB1 : FB2;
            prefetch_chunk(sB_addr + (u32)(nc % 3) * (BSTAGE * 4u), ih, nc & 7, tid, lo);
            cpa_commit();
        }

        if (c == 8) {
            // epilogue1: P -> quant/leaky -> split -> sH; re-init acc
#pragma unroll
            for (int mt = 0; mt < 2; mt++) {
                const int r0 = mw + mt * 16 + g;
#pragma unroll
                for (int nb = 0; nb < 8; nb++) {
                    const int k2p = nw / 2 + nb * 4 + q;
                    float p0 = acc[mt][nb][0], p1 = acc[mt][nb][1];
                    float p2 = acc[mt][nb][2], p3 = acc[mt][nb][3];
                    if (MODE == 1) {
                        p0 = quant_mul(p0, INV_Q1, -67.0f);
                        p1 = quant_mul(p1, INV_Q1, -67.0f);
                        p2 = quant_mul(p2, INV_Q1, -67.0f);
                        p3 = quant_mul(p3, INV_Q1, -67.0f);
                    }
                    p0 = leakyf(p0); p1 = leakyf(p1);
                    p2 = leakyf(p2); p3 = leakyf(p3);
                    u32 hi, lo;
                    split2(p0, p1, hi, lo);
                    int ai = aidx(r0, k2p);
                    sHhi[ai] = hi;  sHlo[ai] = lo;
                    split2(p2, p3, hi, lo);
                    ai = aidx(r0 + 8, k2p);
                    sHhi[ai] = hi;  sHlo[ai] = lo;
                }
            }
#pragma unroll
            for (int nb = 0; nb < 8; nb++) {
                const int cn = nw + nb * 8 + q * 2;
                float b0 = blc[cn], b1 = blc[cn + 1];
#pragma unroll
                for (int mt = 0; mt < 2; mt++) {
                    acc[mt][nb][0] = b0; acc[mt][nb][1] = b1;
                    acc[mt][nb][2] = b0; acc[mt][nb][3] = b1;
                }
            }
            __syncthreads();
        }

        // ---- MMA on chunk c (ldmatrix; 3- or 2-product per FB flag)
        const bool fullB = (c < 8) ? FB1 : FB2;
        const int cc = c & 7;
        const u32 stOff = (u32)(c % 3) * (BSTAGE * 4u);
#pragma unroll
        for (int sp = 0; sp < 2; sp++) {
            u32 ah[2][4], al[2][4];
#pragma unroll
            for (int mt = 0; mt < 2; mt++) {
                const int colA = cc * 4 + sp * 2 + aColBase;
                const u32 aoff = (u32)((colA ^ aXor[mt]) << 4);
                ldm_x4(ah[mt], aRow[mt] + aoff);
                ldm_x4(al[mt], aRow[mt] + aoff + (u32)ALO_OFF);
            }
#pragma unroll
            for (int nbp = 0; nbp < 4; nbp++) {
                const int colB = sp * 2 + bColBase;
                const u32 bo = bRow[nbp] + stOff + (u32)((colB ^ bXor[nbp]) << 4);
                u32 bh[4], bl[4];
                ldm_x4(bh, bo);
                if (fullB) ldm_x4(bl, bo + (u32)(BHALF * 4));
#pragma unroll
                for (int j = 0; j < 2; j++) {
                    const int nb = nbp * 2 + j;
#pragma unroll
                    for (int mt = 0; mt < 2; mt++) {
                        mma16816(acc[mt][nb], ah[mt], bh[2 * j], bh[2 * j + 1]);
                        mma16816(acc[mt][nb], al[mt], bh[2 * j], bh[2 * j + 1]);
                        if (fullB)
                            mma16816(acc[mt][nb], ah[mt], bl[2 * j], bl[2 * j + 1]);
                    }
                }
            }
        }
    }

    // ---- final epilogue: residual + mode outputs (+ next ci stream)
#pragma unroll
    for (int mt = 0; mt < 2; mt++) {
#pragma unroll
        for (int nb = 0; nb < 8; nb++) {
            const int cn = nw + nb * 8 + q * 2;
#pragma unroll
            for (int half = 0; half < 2; half++) {
                const int l = l0 + mw + mt * 16 + g + half * 8;
                if (l >= LFRAMES) continue;
                float o0 = acc[mt][nb][half * 2];
                float o1 = acc[mt][nb][half * 2 + 1];
                float2 r = *(const float2*)(src + (size_t)l * C + cn);
                float2 val, civ;
                if (MODE == 1) {
                    val.x = quant_mul(r.x + (o0 - 16.0f) * 6.528060436248779f, INV_RQ1, -23.0f);
                    val.y = quant_mul(r.y + (o1 - 16.0f) * 6.528060436248779f, INV_RQ1, -23.0f);
                    civ.x = sLUT[(int)val.x + 128];
                    civ.y = sLUT[(int)val.y + 128];
                } else if (MODE == 2) {
                    val.x = o0 + r.x;
                    val.y = o1 + r.y;
                    civ.x = quant_mul((leakyf(val.x) + 38.0f) * S3, INV_S3, 38.0f);
                    civ.y = quant_mul((leakyf(val.y) + 38.0f) * S3, INV_S3, 38.0f);
                } else {
                    val.x = (leakyf(o0 + r.x) + 34.0f) * 3.698859930038452f;
                    val.y = (leakyf(o1 + r.y) + 34.0f) * 3.698859930038452f;
                }
                *(float2*)(dst + (size_t)l * C + cn) = val;
                if (MODE != 3) *(float2*)(ciOut + (size_t)l * C + cn) = civ;
            }
        }
    }
}

// -------------------------------------------------------------------------
extern "C" void kernel_launch(void* const* d_in, const int* in_sizes, int n_in,
                              void* d_out, int out_size)
{
    (void)in_sizes; (void)n_in; (void)out_size;
    const float* x    = (const float*)d_in[0];
    const float* fb   = (const float*)d_in[1];
    const float* r1b  = (const float*)d_in[2];
    const float* r2b  = (const float*)d_in[3];
    const float* r3b  = (const float*)d_in[4];
    const float* wf   = (const float*)d_in[5];
    const float* bf   = (const float*)d_in[6];
    const float* wdw1 = (const float*)d_in[7],  *bdw1 = (const float*)d_in[8];
    const float* wpw1 = (const float*)d_in[9],  *bpw1 = (const float*)d_in[10];
    const float* wlc1 = (const float*)d_in[11], *blc1 = (const float*)d_in[12];
    const float* wdw2 = (const float*)d_in[13], *bdw2 = (const float*)d_in[14];
    const float* wpw2 = (const float*)d_in[15], *bpw2 = (const float*)d_in[16];
    const float* wlc2 = (const float*)d_in[17], *blc2 = (const float*)d_in[18];
    const float* wdw3 = (const float*)d_in[19], *bdw3 = (const float*)d_in[20];
    const float* wpw3 = (const float*)d_in[21], *bpw3 = (const float*)d_in[22];
    const float* wlc3 = (const float*)d_in[23], *blc3 = (const float*)d_in[24];
    float* out = (float*)d_out;

    float *bufA, *bufB, *bufC, *bufD;
    u32* img;
    cudaGetSymbolAddress((void**)&bufA, g_bufA);
    cudaGetSymbolAddress((void**)&bufB, g_bufB);
    cudaGetSymbolAddress((void**)&bufC, g_bufC);
    cudaGetSymbolAddress((void**)&bufD, g_bufD);
    cudaGetSymbolAddress((void**)&img,  g_Bimg);

    const int SMB = (2 * TL * ASTRIDE + 256 + 3 * BSTAGE) * 4;  // 230,400 B
    cudaFuncSetAttribute((const void*)k_block<1, 1, true, true>,
                         cudaFuncAttributeMaxDynamicSharedMemorySize, SMB);
    cudaFuncSetAttribute((const void*)k_block<2, 3, true, true>,
                         cudaFuncAttributeMaxDynamicSharedMemorySize, SMB);
    cudaFuncSetAttribute((const void*)k_block<3, 9, false, false>,
                         cudaFuncAttributeMaxDynamicSharedMemorySize, SMB);

    k_prep<<<dim3(128, 6), 256>>>(wpw1, wlc1, wpw2, wlc2, wpw3, wlc3);
    k_first<<<LFRAMES / TLF, 256>>>(x, fb, wf, bf, bufA, bufC);
    k_block<1, 1, true, true><<<NBLK, NTH, SMB>>>(
        bufA, bufC, r1b, wdw1, bdw1, bpw1, blc1, img + 0 * BIMG, bufB, bufD);
    k_block<2, 3, true, true><<<NBLK, NTH, SMB>>>(
        bufB, bufD, r2b, wdw2, bdw2, bpw2, blc2, img + 4 * BIMG, bufA, bufC);
    k_block<3, 9, false, false><<<NBLK, NTH, SMB>>>(
        bufA, bufC, r3b, wdw3, bdw3, bpw3, blc3, img + 8 * BIMG, out, nullptr);
}